// round 12
// baseline (speedup 1.0000x reference)
#include <cuda_runtime.h>
#include <cuda_fp16.h>
#include <cstdint>

// Problem constants (fixed by the dataset)
#define T_TOK   16384
#define D_DIM   4096
#define E_EXP   64
#define BM      128             // tokens per block
#define BK      64              // fp32 k per chunk (4 k16 steps, kh-split over consumer pairs)
#define NCHUNK  (D_DIM / BK)    // 64
#define NBLK    (T_TOK / BM)    // 128
#define NT      384             // 8 consumer warps + 4 producer warps
#define NCONS   256
#define NSTAGE  3

// fp16 plane tiles, row stride 144 B (128B data + 16B pad -> LDSM conflict-free)
#define RSB       144
#define AH_O      0
#define AL_O      18432          // 128 rows * 144
#define BH_O      36864
#define BL_O      46080          // + 64 * 144
#define STAGE_SZ  55296
#define SMEM_BYTES (NSTAGE * STAGE_SZ)   // 165888; Ls[128][65]=33280 overlays stage0

static __device__ float g_ssum[NBLK * E_EXP];
static __device__ int   g_cnt [NBLK * E_EXP];
static __device__ int   g_arrived;   // zero-init; reset by last block each launch

// ---------- helpers ----------
__device__ __forceinline__ uint32_t smem_u32(const void* p) {
    uint32_t a;
    asm("{ .reg .u64 t; cvta.to.shared.u64 t, %1; cvt.u32.u64 %0, t; }" : "=r"(a) : "l"(p));
    return a;
}
__device__ __forceinline__ void cvt_split2(float x0, float x1, uint32_t& h, uint32_t& lo) {
    __half2 hh = __floats2half2_rn(x0, x1);          // low = x0, high = x1
    h = *reinterpret_cast<uint32_t*>(&hh);
    float2 hf = __half22float2(hh);
    __half2 ll = __floats2half2_rn(x0 - hf.x, x1 - hf.y);
    lo = *reinterpret_cast<uint32_t*>(&ll);
}
__device__ __forceinline__ void st2u(uint32_t a, uint32_t x, uint32_t y) {
    asm volatile("st.shared.v2.u32 [%0], {%1,%2};" :: "r"(a), "r"(x), "r"(y));
}
__device__ __forceinline__ void ldsm4(uint32_t a, uint32_t* r) {
    asm volatile("ldmatrix.sync.aligned.m8n8.x4.shared.b16 {%0,%1,%2,%3}, [%4];"
                 : "=r"(r[0]), "=r"(r[1]), "=r"(r[2]), "=r"(r[3]) : "r"(a));
}
__device__ __forceinline__ void mma_f16(float* d, const uint32_t* a, const uint32_t* b) {
    asm volatile(
        "mma.sync.aligned.m16n8k16.row.col.f32.f16.f16.f32 "
        "{%0,%1,%2,%3}, {%4,%5,%6,%7}, {%8,%9}, {%0,%1,%2,%3};"
        : "+f"(d[0]), "+f"(d[1]), "+f"(d[2]), "+f"(d[3])
        : "r"(a[0]), "r"(a[1]), "r"(a[2]), "r"(a[3]), "r"(b[0]), "r"(b[1]));
}
#define BAR_SYNC(id)   asm volatile("bar.sync %0, %1;"   :: "r"(id), "n"(NT) : "memory")
#define BAR_ARRIVE(id) asm volatile("bar.arrive %0, %1;" :: "r"(id), "n"(NT) : "memory")
// barrier ids: full(s)=1+s (1..3), empty(s)=4+s (4..6); id 0 = __syncthreads
// bar.arrive/bar.sync carry CTA release/acquire ordering: no membar needed.

// ---------- single fused kernel (warp-specialized, 3-stage) ----------
__global__ void __launch_bounds__(NT, 1)
gate_main(const float* __restrict__ inp, const float* __restrict__ W,
          const float* __restrict__ bias, float* __restrict__ out)
{
    extern __shared__ char dsm[];
    __shared__ float s_inv[BM];
    __shared__ float s_ps[NCONS];
    __shared__ float s_b[E_EXP];
    __shared__ int   s_cnt[E_EXP];
    __shared__ int   s_last;
    __shared__ float rs2[NCONS];
    __shared__ int   rc2[NCONS];

    const uint32_t sb = smem_u32(dsm);
    const int tid = threadIdx.x;
    const int blk = blockIdx.x;
    const int w   = tid >> 5;
    const int l   = tid & 31;
    const int l4  = l >> 2;
    const int lk  = l & 3;

    if (tid < E_EXP) { s_b[tid] = bias[tid]; s_cnt[tid] = 0; }
    __syncthreads();

    if (w >= 8) {
        // ================= PRODUCER warps (w8-11, one per SMSP) =================
        const int ptid = tid - NCONS;   // 0..127
        const float4* baseA = (const float4*)(inp + (size_t)blk * BM * D_DIM);
        const float4* baseW = (const float4*)W;
        float4 buf[24];   // A: p 0..15 (2048 f4), W: p 16..23 (1024 f4)

        #define LDG_CHUNK(cc)                                                           \
            _Pragma("unroll")                                                           \
            for (int p = 0; p < 24; ++p) {                                              \
                if (p < 16) {                                                           \
                    int fid = p * 128 + ptid;                                           \
                    buf[p] = __ldcs(&baseA[(fid >> 4) * (D_DIM / 4) + (cc) * 16 + (fid & 15)]); \
                } else {                                                                \
                    int wf = (p - 16) * 128 + ptid;                                     \
                    buf[p] = __ldg(&baseW[(wf >> 4) * (D_DIM / 4) + (cc) * 16 + (wf & 15)]);    \
                }                                                                       \
            }
        #define STS_CHUNK(tb)                                                           \
            _Pragma("unroll")                                                           \
            for (int p = 0; p < 24; ++p) {                                              \
                uint32_t h01, l01, h23, l23, ad, lo;                                    \
                cvt_split2(buf[p].x, buf[p].y, h01, l01);                               \
                cvt_split2(buf[p].z, buf[p].w, h23, l23);                               \
                if (p < 16) {                                                           \
                    int fid = p * 128 + ptid;                                           \
                    ad = (tb) + (uint32_t)((fid >> 4) * RSB + (fid & 15) * 8);          \
                    lo = AL_O;                                                          \
                } else {                                                                \
                    int wf = (p - 16) * 128 + ptid;                                     \
                    ad = (tb) + BH_O + (uint32_t)((wf >> 4) * RSB + (wf & 15) * 8);     \
                    lo = BL_O - BH_O;                                                   \
                }                                                                       \
                st2u(ad, h01, h23);                                                     \
                st2u(ad + lo, l01, l23);                                                \
            }

        // ramp: stage chunks 0,1,2
        LDG_CHUNK(0); STS_CHUNK(sb);                BAR_ARRIVE(1);
        LDG_CHUNK(1); STS_CHUNK(sb + STAGE_SZ);     BAR_ARRIVE(2);
        LDG_CHUNK(2); STS_CHUNK(sb + 2 * STAGE_SZ); BAR_ARRIVE(3);
        LDG_CHUNK(3);

        int s = 0;
        for (int c = 3; c < NCHUNK; ++c) {
            BAR_SYNC(4 + s);                    // wait empty (consumers done with c-3)
            STS_CHUNK(sb + s * STAGE_SZ);
            BAR_ARRIVE(1 + s);                  // full(c)  (bar release orders the STS)
            if (c + 1 < NCHUNK) { LDG_CHUNK(c + 1); }
            s = (s == 2) ? 0 : s + 1;
        }
    } else {
        // ================= CONSUMER warps (w0-7) =================
        const int tg = (w >> 2) & 1;   // 2 token groups of 64
        const int eg = (w >> 1) & 1;   // 2 expert groups of 32
        const int kh = w & 1;          // k16-step pair split

        uint32_t aLd[4];
#pragma unroll
        for (int i = 0; i < 4; ++i)
            aLd[i] = (uint32_t)((tg * 64 + i * 16 + ((l >> 3) & 1) * 8 + (l & 7)) * RSB
                                + (l >> 4) * 16);
        uint32_t bLd[2];
#pragma unroll
        for (int jp = 0; jp < 2; ++jp)
            bLd[jp] = (uint32_t)(BH_O + (eg * 32 + jp * 16 + (l >> 4) * 8 + (l & 7)) * RSB
                                 + ((l >> 3) & 1) * 16);

        float acc[4][4][4];
#pragma unroll
        for (int i = 0; i < 4; ++i)
#pragma unroll
            for (int j = 0; j < 4; ++j)
#pragma unroll
                for (int r = 0; r < 4; ++r) acc[i][j][r] = 0.f;

        int s = 0;
        for (int c = 0; c < NCHUNK; ++c) {
            BAR_SYNC(1 + s);             // wait full (acquire)
            const uint32_t tb = sb + s * STAGE_SZ;
#pragma unroll
            for (int ks2 = 0; ks2 < 2; ++ks2) {
                const uint32_t ko = (uint32_t)((kh * 2 + ks2) * 32);
                uint32_t aH[4][4], aL[4][4], bHf[4][2], bLf[4][2];
#pragma unroll
                for (int i = 0; i < 4; ++i) {
                    ldsm4(tb + aLd[i] + ko,        aH[i]);
                    ldsm4(tb + aLd[i] + ko + AL_O, aL[i]);
                }
#pragma unroll
                for (int jp = 0; jp < 2; ++jp) {
                    uint32_t r[4];
                    ldsm4(tb + bLd[jp] + ko, r);
                    bHf[jp * 2][0] = r[0]; bHf[jp * 2][1] = r[1];
                    bHf[jp * 2 + 1][0] = r[2]; bHf[jp * 2 + 1][1] = r[3];
                    ldsm4(tb + bLd[jp] + ko + (BL_O - BH_O), r);
                    bLf[jp * 2][0] = r[0]; bLf[jp * 2][1] = r[1];
                    bLf[jp * 2 + 1][0] = r[2]; bLf[jp * 2 + 1][1] = r[3];
                }
#pragma unroll
                for (int i = 0; i < 4; ++i)
#pragma unroll
                    for (int j = 0; j < 4; ++j)
                        mma_f16(acc[i][j], aH[i], bHf[j]);
#pragma unroll
                for (int i = 0; i < 4; ++i)
#pragma unroll
                    for (int j = 0; j < 4; ++j)
                        mma_f16(acc[i][j], aH[i], bLf[j]);
#pragma unroll
                for (int i = 0; i < 4; ++i)
#pragma unroll
                    for (int j = 0; j < 4; ++j)
                        mma_f16(acc[i][j], aL[i], bHf[j]);
            }
            // all MMAs consumed the fragments -> LDSMs retired -> buffer reusable
            BAR_ARRIVE(4 + s);
            s = (s == 2) ? 0 : s + 1;
        }

        __syncthreads();   // join producers (bar 0)

        float* Ls = (float*)dsm;   // [128][65], overlays stage0
        for (int idx = tid; idx < BM * 65; idx += NCONS) Ls[idx] = 0.f;
        __syncthreads();
#pragma unroll
        for (int i = 0; i < 4; ++i) {
            int t0 = tg * 64 + i * 16 + l4;
#pragma unroll
            for (int j = 0; j < 4; ++j) {
                int e0 = eg * 32 + j * 8 + lk * 2;
                atomicAdd(&Ls[t0 * 65 + e0],           acc[i][j][0]);   // 2 kh addends:
                atomicAdd(&Ls[t0 * 65 + e0 + 1],       acc[i][j][1]);   // commutative ->
                atomicAdd(&Ls[(t0 + 8) * 65 + e0],     acc[i][j][2]);   // deterministic
                atomicAdd(&Ls[(t0 + 8) * 65 + e0 + 1], acc[i][j][3]);
            }
        }
        goto epilogue_join;
    }
    // producers join the two consumer syncs above
    __syncthreads();
    __syncthreads();
epilogue_join:
    __syncthreads();

    // ---- per-token softmax / argmax (threads 0..127); store exp() back ----
    {
        float* Ls = (float*)dsm;
        if (tid < BM) {
            float* lr = &Ls[tid * 65];
            float m = -1e30f; int am = 0;
#pragma unroll
            for (int e = 0; e < E_EXP; ++e) {
                float v = lr[e] + s_b[e];
                lr[e] = v;
                if (v > m) { m = v; am = e; }
            }
            float den = 0.f;
#pragma unroll
            for (int e = 0; e < E_EXP; ++e) {
                float p = expf(lr[e] - m);
                lr[e] = p;
                den += p;
            }
            float inv = 1.f / den;
            s_inv[tid] = inv;
            atomicAdd(&s_cnt[am], 1);          // int atomic: value-deterministic
            int gt = blk * BM + tid;
            out[gt]         = (float)am;       // pruned_idx (capacity 39322 > T: never pruned)
            out[T_TOK + gt] = inv;             // top1 score = exp(0)/den
        }
        __syncthreads();

        // per-expert score partial sums (fixed deterministic order; 4 slices of 32 tokens)
        if (tid < NCONS) {
            int e = tid & 63, h = tid >> 6;
            float s2 = 0.f;
#pragma unroll
            for (int i = 0; i < 32; ++i) {
                int t = h * 32 + i;
                s2 += Ls[t * 65 + e] * s_inv[t];
            }
            s_ps[tid] = s2;
        }
        __syncthreads();
        if (tid < E_EXP) {
            g_ssum[blk * E_EXP + tid] = s_ps[tid] + s_ps[64 + tid] + s_ps[128 + tid] + s_ps[192 + tid];
            g_cnt [blk * E_EXP + tid] = s_cnt[tid];
        }
    }
    __syncthreads();

    // ---- fused loss: last block reduces (deterministic fixed-order) ----
    if (tid == 0) {
        __threadfence();
        int n = atomicAdd(&g_arrived, 1);
        s_last = (n == NBLK - 1) ? 1 : 0;
    }
    __syncthreads();
    if (s_last) {
        __threadfence();
        if (tid < NCONS) {
            int e = tid & 63, h = tid >> 6;      // 4 groups of 32 blocks
            float ss = 0.f; int c = 0;
#pragma unroll
            for (int b = h * 32; b < h * 32 + 32; ++b) {
                ss += g_ssum[b * E_EXP + e];
                c  += g_cnt [b * E_EXP + e];
            }
            rs2[tid] = ss; rc2[tid] = c;
        }
        __syncthreads();
        if (tid < E_EXP) {
            float S = rs2[tid] + rs2[64 + tid] + rs2[128 + tid] + rs2[192 + tid];
            int   C = rc2[tid] + rc2[64 + tid] + rc2[128 + tid] + rc2[192 + tid];
            rs2[tid] = S * (float)C;
        }
        __syncthreads();
        if (tid == 0) {
            float tot = 0.f;
#pragma unroll
            for (int e2 = 0; e2 < E_EXP; ++e2) tot += rs2[e2];
            out[2 * T_TOK] = tot * (float)E_EXP / ((float)T_TOK * (float)T_TOK);
            g_arrived = 0;   // reset for next graph replay
        }
    }
}

extern "C" void kernel_launch(void* const* d_in, const int* in_sizes, int n_in,
                              void* d_out, int out_size)
{
    const float* inp  = (const float*)d_in[0];
    const float* W    = (const float*)d_in[1];
    const float* bias = (const float*)d_in[2];
    float* out = (float*)d_out;   // [0,T) idx, [T,2T) top1 score, [2T] loss

    cudaFuncSetAttribute(gate_main, cudaFuncAttributeMaxDynamicSharedMemorySize, SMEM_BYTES);
    gate_main<<<NBLK, NT, SMEM_BYTES>>>(inp, W, bias, out);
}

// round 13
// speedup vs baseline: 1.1405x; 1.1405x over previous
#include <cuda_runtime.h>
#include <cuda_fp16.h>
#include <cstdint>

// Problem constants (fixed by the dataset)
#define T_TOK   16384
#define D_DIM   4096
#define E_EXP   64
#define BM      128             // tokens per block
#define BK      64              // fp32 k per chunk (4 k16 steps; kh pairs split them)
#define NCHUNK  (D_DIM / BK)    // 64
#define NBLK    (T_TOK / BM)    // 128
#define NT      512             // 16 homogeneous warps, 4 per SMSP

// fp16 plane tiles, row stride 144 B (128B data + 16B pad -> LDSM conflict-free)
#define RSB       144
#define AH_O      0
#define AL_O      18432          // 128 rows * 144
#define BH_O      36864
#define BL_O      46080          // + 64 * 144
#define STAGE_SZ  55296
#define SMEM_BYTES (2 * STAGE_SZ)   // 110592; Ls[128][65]=33280 overlays stage0

static __device__ float g_ssum[NBLK * E_EXP];
static __device__ int   g_cnt [NBLK * E_EXP];
static __device__ int   g_arrived;   // zero-init; reset by last block each launch

// ---------- helpers ----------
__device__ __forceinline__ uint32_t smem_u32(const void* p) {
    uint32_t a;
    asm("{ .reg .u64 t; cvta.to.shared.u64 t, %1; cvt.u32.u64 %0, t; }" : "=r"(a) : "l"(p));
    return a;
}
__device__ __forceinline__ void cvt_split2(float x0, float x1, uint32_t& h, uint32_t& lo) {
    __half2 hh = __floats2half2_rn(x0, x1);          // low = x0, high = x1
    h = *reinterpret_cast<uint32_t*>(&hh);
    float2 hf = __half22float2(hh);
    __half2 ll = __floats2half2_rn(x0 - hf.x, x1 - hf.y);
    lo = *reinterpret_cast<uint32_t*>(&ll);
}
__device__ __forceinline__ void st2u(uint32_t a, uint32_t x, uint32_t y) {
    asm volatile("st.shared.v2.u32 [%0], {%1,%2};" :: "r"(a), "r"(x), "r"(y));
}
__device__ __forceinline__ void ldsm4(uint32_t a, uint32_t* r) {
    asm volatile("ldmatrix.sync.aligned.m8n8.x4.shared.b16 {%0,%1,%2,%3}, [%4];"
                 : "=r"(r[0]), "=r"(r[1]), "=r"(r[2]), "=r"(r[3]) : "r"(a));
}
__device__ __forceinline__ void mma_f16(float* d, const uint32_t* a, const uint32_t* b) {
    asm volatile(
        "mma.sync.aligned.m16n8k16.row.col.f32.f16.f16.f32 "
        "{%0,%1,%2,%3}, {%4,%5,%6,%7}, {%8,%9}, {%0,%1,%2,%3};"
        : "+f"(d[0]), "+f"(d[1]), "+f"(d[2]), "+f"(d[3])
        : "r"(a[0]), "r"(a[1]), "r"(a[2]), "r"(a[3]), "r"(b[0]), "r"(b[1]));
}

// ---------- single fused kernel (16 warps, homogeneous) ----------
__global__ void __launch_bounds__(NT, 1)
gate_main(const float* __restrict__ inp, const float* __restrict__ W,
          const float* __restrict__ bias, float* __restrict__ out)
{
    extern __shared__ char dsm[];
    __shared__ float s_inv[BM];
    __shared__ float s_ps[NT];
    __shared__ float s_b[E_EXP];
    __shared__ int   s_cnt[E_EXP];
    __shared__ int   s_last;
    __shared__ float rs2[NT];
    __shared__ int   rc2[NT];

    const uint32_t sb = smem_u32(dsm);
    const int tid = threadIdx.x;
    const int blk = blockIdx.x;
    const int w   = tid >> 5;
    const int l   = tid & 31;
    const int l4  = l >> 2;
    const int lk  = l & 3;
    const int tg  = w & 3;          // 4 token groups of 32
    const int eg  = (w >> 2) & 1;   // 2 expert groups of 32
    const int kh  = (w >> 3) & 1;   // k16-step pair split (2 addends per logit)

    if (tid < E_EXP) { s_b[tid] = bias[tid]; s_cnt[tid] = 0; }

    // ---- staging: A 2048 f4/chunk / 512 thr = 4 ; W 1024/512 = 2 ----
    const float4* baseA = (const float4*)(inp + (size_t)blk * BM * D_DIM);
    const float4* baseW = (const float4*)W;
    int offA[4]; uint32_t stA[4];
#pragma unroll
    for (int p = 0; p < 4; ++p) {
        int fid = p * NT + tid, row = fid >> 4, q4 = fid & 15;
        offA[p] = row * (D_DIM / 4) + q4;
        stA[p]  = (uint32_t)(row * RSB + q4 * 8);
    }
    int offW[2]; uint32_t stW[2];
#pragma unroll
    for (int p = 0; p < 2; ++p) {
        int fid = p * NT + tid, row = fid >> 4, q4 = fid & 15;
        offW[p] = row * (D_DIM / 4) + q4;
        stW[p]  = (uint32_t)(BH_O + row * RSB + q4 * 8);
    }

    // ---- ldmatrix per-lane base addresses ----
    // A x4: g0 rows m..m+7 klo | g1 m+8..m+15 klo | g2 m..m+7 khi | g3 m+8.. khi
    uint32_t aLd[2];
#pragma unroll
    for (int i = 0; i < 2; ++i)
        aLd[i] = (uint32_t)((tg * 32 + i * 16 + ((l >> 3) & 1) * 8 + (l & 7)) * RSB
                            + (l >> 4) * 16);
    // B x4 (non-trans; W[n][k] row-major == KxN col-major)
    uint32_t bLd[2];
#pragma unroll
    for (int jp = 0; jp < 2; ++jp)
        bLd[jp] = (uint32_t)(BH_O + (eg * 32 + jp * 16 + (l >> 4) * 8 + (l & 7)) * RSB
                             + ((l >> 3) & 1) * 16);

    float acc[2][4][4];
#pragma unroll
    for (int i = 0; i < 2; ++i)
#pragma unroll
        for (int j = 0; j < 4; ++j)
#pragma unroll
            for (int r = 0; r < 4; ++r) acc[i][j][r] = 0.f;

    float4 ra[4], rw[2];
#pragma unroll
    for (int p = 0; p < 4; ++p) ra[p] = baseA[offA[p]];
#pragma unroll
    for (int p = 0; p < 2; ++p) rw[p] = baseW[offW[p]];

    for (int c = 0; c < NCHUNK; ++c) {
        const uint32_t tb = sb + (c & 1) * STAGE_SZ;
        // split fp32 -> fp16 hi/lo planes (8B stores, phase-conflict-free)
#pragma unroll
        for (int p = 0; p < 4; ++p) {
            uint32_t h01, l01, h23, l23;
            cvt_split2(ra[p].x, ra[p].y, h01, l01);
            cvt_split2(ra[p].z, ra[p].w, h23, l23);
            st2u(tb + stA[p],        h01, h23);
            st2u(tb + stA[p] + AL_O, l01, l23);
        }
#pragma unroll
        for (int p = 0; p < 2; ++p) {
            uint32_t h01, l01, h23, l23;
            cvt_split2(rw[p].x, rw[p].y, h01, l01);
            cvt_split2(rw[p].z, rw[p].w, h23, l23);
            st2u(tb + stW[p],                  h01, h23);
            st2u(tb + stW[p] + (BL_O - BH_O),  l01, l23);
        }
        __syncthreads();   // dbl-buffer: buffer written here was last read before prev sync

        if (c + 1 < NCHUNK) {
#pragma unroll
            for (int p = 0; p < 4; ++p) ra[p] = baseA[offA[p] + (c + 1) * (BK / 4)];
#pragma unroll
            for (int p = 0; p < 2; ++p) rw[p] = baseW[offW[p] + (c + 1) * (BK / 4)];
        }

        // this warp's two k16 steps (kh pair covers the other two)
#pragma unroll
        for (int ks2 = 0; ks2 < 2; ++ks2) {
            const uint32_t ko = (uint32_t)((kh * 2 + ks2) * 32);
            uint32_t aH[2][4], aL[2][4], bHf[4][2], bLf[4][2];
#pragma unroll
            for (int i = 0; i < 2; ++i) {
                ldsm4(tb + aLd[i] + ko,        aH[i]);
                ldsm4(tb + aLd[i] + ko + AL_O, aL[i]);
            }
#pragma unroll
            for (int jp = 0; jp < 2; ++jp) {
                uint32_t r[4];
                ldsm4(tb + bLd[jp] + ko, r);
                bHf[jp * 2][0] = r[0]; bHf[jp * 2][1] = r[1];
                bHf[jp * 2 + 1][0] = r[2]; bHf[jp * 2 + 1][1] = r[3];
                ldsm4(tb + bLd[jp] + ko + (BL_O - BH_O), r);
                bLf[jp * 2][0] = r[0]; bLf[jp * 2][1] = r[1];
                bLf[jp * 2 + 1][0] = r[2]; bLf[jp * 2 + 1][1] = r[3];
            }
            // 3 term-rounds of 8 independent MMAs
#pragma unroll
            for (int i = 0; i < 2; ++i)
#pragma unroll
                for (int j = 0; j < 4; ++j)
                    mma_f16(acc[i][j], aH[i], bHf[j]);
#pragma unroll
            for (int i = 0; i < 2; ++i)
#pragma unroll
                for (int j = 0; j < 4; ++j)
                    mma_f16(acc[i][j], aH[i], bLf[j]);
#pragma unroll
            for (int i = 0; i < 2; ++i)
#pragma unroll
                for (int j = 0; j < 4; ++j)
                    mma_f16(acc[i][j], aL[i], bHf[j]);
        }
    }
    __syncthreads();   // compute done before logits overlay tile buffers

    // ---- epilogue: zero Ls, merge kh pairs via 2-addend atomicAdd (deterministic) ----
    float* Ls = (float*)dsm;   // [128][65]
    for (int idx = tid; idx < BM * 65; idx += NT) Ls[idx] = 0.f;
    __syncthreads();
#pragma unroll
    for (int i = 0; i < 2; ++i) {
        int t0 = tg * 32 + i * 16 + l4;
#pragma unroll
        for (int j = 0; j < 4; ++j) {
            int e0 = eg * 32 + j * 8 + lk * 2;
            atomicAdd(&Ls[t0 * 65 + e0],           acc[i][j][0]);   // 2 commuting addends
            atomicAdd(&Ls[t0 * 65 + e0 + 1],       acc[i][j][1]);
            atomicAdd(&Ls[(t0 + 8) * 65 + e0],     acc[i][j][2]);
            atomicAdd(&Ls[(t0 + 8) * 65 + e0 + 1], acc[i][j][3]);
        }
    }
    __syncthreads();

    // per-token softmax / argmax (threads 0..127); store exp() back
    if (tid < BM) {
        float* lr = &Ls[tid * 65];
        float m = -1e30f; int am = 0;
#pragma unroll
        for (int e = 0; e < E_EXP; ++e) {
            float v = lr[e] + s_b[e];
            lr[e] = v;
            if (v > m) { m = v; am = e; }
        }
        float den = 0.f;
#pragma unroll
        for (int e = 0; e < E_EXP; ++e) {
            float p = expf(lr[e] - m);
            lr[e] = p;
            den += p;
        }
        float inv = 1.f / den;
        s_inv[tid] = inv;
        atomicAdd(&s_cnt[am], 1);          // int atomic: value-deterministic
        int gt = blk * BM + tid;
        out[gt]         = (float)am;       // pruned_idx (capacity 39322 > T: never pruned)
        out[T_TOK + gt] = inv;             // top1 score = exp(0)/den
    }
    __syncthreads();

    // per-expert score partial sums (fixed deterministic order; 8 slices of 16 tokens)
    {
        int e = tid & 63, h = tid >> 6;
        float s = 0.f;
#pragma unroll
        for (int i = 0; i < 16; ++i) {
            int t = h * 16 + i;
            s += Ls[t * 65 + e] * s_inv[t];
        }
        s_ps[tid] = s;
    }
    __syncthreads();
    if (tid < E_EXP) {
        float S = 0.f;
#pragma unroll
        for (int g = 0; g < 8; ++g) S += s_ps[g * 64 + tid];
        g_ssum[blk * E_EXP + tid] = S;
        g_cnt [blk * E_EXP + tid] = s_cnt[tid];
    }
    __syncthreads();

    // ---- fused loss: last block reduces (deterministic fixed-order) ----
    if (tid == 0) {
        __threadfence();
        int n = atomicAdd(&g_arrived, 1);
        s_last = (n == NBLK - 1) ? 1 : 0;
    }
    __syncthreads();
    if (s_last) {
        __threadfence();
        int e = tid & 63, h = tid >> 6;      // 8 groups of 16 blocks
        float ss = 0.f; int c = 0;
#pragma unroll
        for (int b = h * 16; b < h * 16 + 16; ++b) {
            ss += g_ssum[b * E_EXP + e];
            c  += g_cnt [b * E_EXP + e];
        }
        rs2[tid] = ss; rc2[tid] = c;
        __syncthreads();
        if (tid < E_EXP) {
            float S = 0.f; int C = 0;
#pragma unroll
            for (int g = 0; g < 8; ++g) { S += rs2[g * 64 + tid]; C += rc2[g * 64 + tid]; }
            rs2[tid] = S * (float)C;
        }
        __syncthreads();
        if (tid == 0) {
            float tot = 0.f;
#pragma unroll
            for (int e2 = 0; e2 < E_EXP; ++e2) tot += rs2[e2];
            out[2 * T_TOK] = tot * (float)E_EXP / ((float)T_TOK * (float)T_TOK);
            g_arrived = 0;   // reset for next graph replay
        }
    }
}

extern "C" void kernel_launch(void* const* d_in, const int* in_sizes, int n_in,
                              void* d_out, int out_size)
{
    const float* inp  = (const float*)d_in[0];
    const float* W    = (const float*)d_in[1];
    const float* bias = (const float*)d_in[2];
    float* out = (float*)d_out;   // [0,T) idx, [T,2T) top1 score, [2T] loss

    cudaFuncSetAttribute(gate_main, cudaFuncAttributeMaxDynamicSharedMemorySize, SMEM_BYTES);
    gate_main<<<NBLK, NT, SMEM_BYTES>>>(inp, W, bias, out);
}

// round 14
// speedup vs baseline: 1.1923x; 1.0454x over previous
#include <cuda_runtime.h>
#include <cuda_fp16.h>
#include <cstdint>

// Problem constants (fixed by the dataset)
#define T_TOK   16384
#define D_DIM   4096
#define E_EXP   64
#define BM      128             // tokens per block
#define BK      64              // fp32 k per chunk (4 k16 steps, kh-split over warp pairs)
#define NCHUNK  (D_DIM / BK)    // 64
#define NBLK    (T_TOK / BM)    // 128
#define NT      256

// fp16 plane tiles, row stride 144 B (128B data + 16B pad -> LDSM conflict-free)
#define RSB       144
#define AH_O      0
#define AL_O      18432          // 128 rows * 144
#define BH_O      36864
#define BL_O      46080          // + 64 * 144
#define STAGE_SZ  55296
#define SMEM_BYTES (2 * STAGE_SZ)   // 110592; Ls[128][65]=33280 overlays stage0

static __device__ float g_ssum[NBLK * E_EXP];
static __device__ int   g_cnt [NBLK * E_EXP];
static __device__ int   g_arrived;   // zero-init; reset by last block each launch

// ---------- helpers ----------
__device__ __forceinline__ uint32_t smem_u32(const void* p) {
    uint32_t a;
    asm("{ .reg .u64 t; cvta.to.shared.u64 t, %1; cvt.u32.u64 %0, t; }" : "=r"(a) : "l"(p));
    return a;
}
__device__ __forceinline__ void cvt_split2(float x0, float x1, uint32_t& h, uint32_t& lo) {
    __half2 hh = __floats2half2_rn(x0, x1);          // low = x0, high = x1
    h = *reinterpret_cast<uint32_t*>(&hh);
    float2 hf = __half22float2(hh);
    __half2 ll = __floats2half2_rn(x0 - hf.x, x1 - hf.y);
    lo = *reinterpret_cast<uint32_t*>(&ll);
}
__device__ __forceinline__ void st2u(uint32_t a, uint32_t x, uint32_t y) {
    asm volatile("st.shared.v2.u32 [%0], {%1,%2};" :: "r"(a), "r"(x), "r"(y));
}
__device__ __forceinline__ void ldsm4(uint32_t a, uint32_t* r) {
    asm volatile("ldmatrix.sync.aligned.m8n8.x4.shared.b16 {%0,%1,%2,%3}, [%4];"
                 : "=r"(r[0]), "=r"(r[1]), "=r"(r[2]), "=r"(r[3]) : "r"(a));
}
__device__ __forceinline__ void mma_f16(float* d, const uint32_t* a, const uint32_t* b) {
    asm volatile(
        "mma.sync.aligned.m16n8k16.row.col.f32.f16.f16.f32 "
        "{%0,%1,%2,%3}, {%4,%5,%6,%7}, {%8,%9}, {%0,%1,%2,%3};"
        : "+f"(d[0]), "+f"(d[1]), "+f"(d[2]), "+f"(d[3])
        : "r"(a[0]), "r"(a[1]), "r"(a[2]), "r"(a[3]), "r"(b[0]), "r"(b[1]));
}

// ---------- single fused kernel ----------
__global__ void __launch_bounds__(NT, 1)
gate_main(const float* __restrict__ inp, const float* __restrict__ W,
          const float* __restrict__ bias, float* __restrict__ out)
{
    extern __shared__ char dsm[];
    __shared__ float s_inv[BM];
    __shared__ float s_ps[NT];
    __shared__ float s_b[E_EXP];
    __shared__ int   s_cnt[E_EXP];
    __shared__ int   s_last;
    __shared__ float rs2[NT];
    __shared__ int   rc2[NT];

    const uint32_t sb = smem_u32(dsm);
    const int tid = threadIdx.x;
    const int blk = blockIdx.x;
    const int w   = tid >> 5;
    const int l   = tid & 31;
    const int l4  = l >> 2;
    const int lk  = l & 3;
    const int tg  = (w >> 2) & 1;   // 2 token groups of 64
    const int eg  = (w >> 1) & 1;   // 2 expert groups of 32
    const int kh  = w & 1;          // k16-step pair split

    if (tid < E_EXP) { s_b[tid] = bias[tid]; s_cnt[tid] = 0; }

    // ---- staging: A 2048 f4/chunk / 256 thr = 8 ; W 1024/256 = 4 ----
    const float4* baseA = (const float4*)(inp + (size_t)blk * BM * D_DIM);
    const float4* baseW = (const float4*)W;
    int offA[8]; uint32_t stA[8];
#pragma unroll
    for (int p = 0; p < 8; ++p) {
        int fid = p * NT + tid, row = fid >> 4, q4 = fid & 15;
        offA[p] = row * (D_DIM / 4) + q4;
        stA[p]  = (uint32_t)(row * RSB + q4 * 8);
    }
    int offW[4]; uint32_t stW[4];
#pragma unroll
    for (int p = 0; p < 4; ++p) {
        int fid = p * NT + tid, row = fid >> 4, q4 = fid & 15;
        offW[p] = row * (D_DIM / 4) + q4;
        stW[p]  = (uint32_t)(BH_O + row * RSB + q4 * 8);
    }

    // ---- ldmatrix per-lane base addresses ----
    uint32_t aLd[4];
#pragma unroll
    for (int i = 0; i < 4; ++i)
        aLd[i] = (uint32_t)((tg * 64 + i * 16 + ((l >> 3) & 1) * 8 + (l & 7)) * RSB
                            + (l >> 4) * 16);
    uint32_t bLd[2];
#pragma unroll
    for (int jp = 0; jp < 2; ++jp)
        bLd[jp] = (uint32_t)(BH_O + (eg * 32 + jp * 16 + (l >> 4) * 8 + (l & 7)) * RSB
                             + ((l >> 3) & 1) * 16);

    float acc[4][4][4];
#pragma unroll
    for (int i = 0; i < 4; ++i)
#pragma unroll
        for (int j = 0; j < 4; ++j)
#pragma unroll
            for (int r = 0; r < 4; ++r) acc[i][j][r] = 0.f;

    float4 ra[8], rw[4];

    #define LDG_CHUNK(cc)                                              \
        _Pragma("unroll")                                              \
        for (int p = 0; p < 8; ++p) ra[p] = baseA[offA[p] + (cc) * (BK / 4)]; \
        _Pragma("unroll")                                              \
        for (int p = 0; p < 4; ++p) rw[p] = baseW[offW[p] + (cc) * (BK / 4)];

    #define STS_CHUNK(tb)                                              \
        _Pragma("unroll")                                              \
        for (int p = 0; p < 8; ++p) {                                  \
            uint32_t h01, l01, h23, l23;                               \
            cvt_split2(ra[p].x, ra[p].y, h01, l01);                    \
            cvt_split2(ra[p].z, ra[p].w, h23, l23);                    \
            st2u((tb) + stA[p],        h01, h23);                      \
            st2u((tb) + stA[p] + AL_O, l01, l23);                      \
        }                                                              \
        _Pragma("unroll")                                              \
        for (int p = 0; p < 4; ++p) {                                  \
            uint32_t h01, l01, h23, l23;                               \
            cvt_split2(rw[p].x, rw[p].y, h01, l01);                    \
            cvt_split2(rw[p].z, rw[p].w, h23, l23);                    \
            st2u((tb) + stW[p],                 h01, h23);             \
            st2u((tb) + stW[p] + (BL_O - BH_O), l01, l23);             \
        }

    // ---- ramp: stage chunk 0, prefetch chunk 1 ----
    LDG_CHUNK(0);
    STS_CHUNK(sb);
    LDG_CHUNK(1);
    __syncthreads();

    for (int c = 0; c < NCHUNK; ++c) {
        // STS(c+1) into the other buffer FIRST: staging overlaps this chunk's MMAs.
        // Safe: buf (c+1)&1 was last read in compute(c-1), fenced by the prior sync.
        if (c + 1 < NCHUNK) {
            STS_CHUNK(sb + ((c + 1) & 1) * STAGE_SZ);
            if (c + 2 < NCHUNK) { LDG_CHUNK(c + 2); }
        }

        // compute(c) on buf c&1
        const uint32_t tb = sb + (c & 1) * STAGE_SZ;
#pragma unroll
        for (int ks2 = 0; ks2 < 2; ++ks2) {
            const uint32_t ko = (uint32_t)((kh * 2 + ks2) * 32);
            uint32_t aH[4][4], aL[4][4], bHf[4][2], bLf[4][2];
            // hi-plane fragments first -> hh MMAs can start ASAP;
            // lo-plane LDSMs issue before the MMA bursts and complete under them.
#pragma unroll
            for (int i = 0; i < 4; ++i) ldsm4(tb + aLd[i] + ko, aH[i]);
#pragma unroll
            for (int jp = 0; jp < 2; ++jp) {
                uint32_t r[4];
                ldsm4(tb + bLd[jp] + ko, r);
                bHf[jp * 2][0] = r[0]; bHf[jp * 2][1] = r[1];
                bHf[jp * 2 + 1][0] = r[2]; bHf[jp * 2 + 1][1] = r[3];
            }
#pragma unroll
            for (int jp = 0; jp < 2; ++jp) {
                uint32_t r[4];
                ldsm4(tb + bLd[jp] + ko + (BL_O - BH_O), r);
                bLf[jp * 2][0] = r[0]; bLf[jp * 2][1] = r[1];
                bLf[jp * 2 + 1][0] = r[2]; bLf[jp * 2 + 1][1] = r[3];
            }
#pragma unroll
            for (int i = 0; i < 4; ++i) ldsm4(tb + aLd[i] + ko + AL_O, aL[i]);

#pragma unroll
            for (int i = 0; i < 4; ++i)
#pragma unroll
                for (int j = 0; j < 4; ++j)
                    mma_f16(acc[i][j], aH[i], bHf[j]);
#pragma unroll
            for (int i = 0; i < 4; ++i)
#pragma unroll
                for (int j = 0; j < 4; ++j)
                    mma_f16(acc[i][j], aH[i], bLf[j]);
#pragma unroll
            for (int i = 0; i < 4; ++i)
#pragma unroll
                for (int j = 0; j < 4; ++j)
                    mma_f16(acc[i][j], aL[i], bHf[j]);
        }
        __syncthreads();   // everyone done reading buf c&1 and writing buf (c+1)&1
    }

    // ---- epilogue: zero Ls, merge kh pairs via 2-addend atomicAdd (deterministic) ----
    float* Ls = (float*)dsm;   // [128][65], overlays stage0
    for (int idx = tid; idx < BM * 65; idx += NT) Ls[idx] = 0.f;
    __syncthreads();
#pragma unroll
    for (int i = 0; i < 4; ++i) {
        int t0 = tg * 64 + i * 16 + l4;
#pragma unroll
        for (int j = 0; j < 4; ++j) {
            int e0 = eg * 32 + j * 8 + lk * 2;
            atomicAdd(&Ls[t0 * 65 + e0],           acc[i][j][0]);   // 2 commuting addends
            atomicAdd(&Ls[t0 * 65 + e0 + 1],       acc[i][j][1]);
            atomicAdd(&Ls[(t0 + 8) * 65 + e0],     acc[i][j][2]);
            atomicAdd(&Ls[(t0 + 8) * 65 + e0 + 1], acc[i][j][3]);
        }
    }
    __syncthreads();

    // per-token softmax / argmax (threads 0..127); store exp() back
    if (tid < BM) {
        float* lr = &Ls[tid * 65];
        float m = -1e30f; int am = 0;
#pragma unroll
        for (int e = 0; e < E_EXP; ++e) {
            float v = lr[e] + s_b[e];
            lr[e] = v;
            if (v > m) { m = v; am = e; }
        }
        float den = 0.f;
#pragma unroll
        for (int e = 0; e < E_EXP; ++e) {
            float p = expf(lr[e] - m);
            lr[e] = p;
            den += p;
        }
        float inv = 1.f / den;
        s_inv[tid] = inv;
        atomicAdd(&s_cnt[am], 1);          // int atomic: value-deterministic
        int gt = blk * BM + tid;
        out[gt]         = (float)am;       // pruned_idx (capacity 39322 > T: never pruned)
        out[T_TOK + gt] = inv;             // top1 score = exp(0)/den
    }
    __syncthreads();

    // per-expert score partial sums (fixed deterministic order; 4 slices of 32 tokens)
    {
        int e = tid & 63, h = tid >> 6;
        float s = 0.f;
#pragma unroll
        for (int i = 0; i < 32; ++i) {
            int t = h * 32 + i;
            s += Ls[t * 65 + e] * s_inv[t];
        }
        s_ps[tid] = s;
    }
    __syncthreads();
    if (tid < E_EXP) {
        g_ssum[blk * E_EXP + tid] = s_ps[tid] + s_ps[64 + tid] + s_ps[128 + tid] + s_ps[192 + tid];
        g_cnt [blk * E_EXP + tid] = s_cnt[tid];
    }
    __syncthreads();

    // ---- fused loss: last block reduces (deterministic fixed-order) ----
    if (tid == 0) {
        __threadfence();
        int n = atomicAdd(&g_arrived, 1);
        s_last = (n == NBLK - 1) ? 1 : 0;
    }
    __syncthreads();
    if (s_last) {
        __threadfence();
        int e = tid & 63, h = tid >> 6;      // 4 groups of 32 blocks
        float ss = 0.f; int c = 0;
#pragma unroll
        for (int b = h * 32; b < h * 32 + 32; ++b) {
            ss += g_ssum[b * E_EXP + e];
            c  += g_cnt [b * E_EXP + e];
        }
        rs2[tid] = ss; rc2[tid] = c;
        __syncthreads();
        if (tid < E_EXP) {
            float S = rs2[tid] + rs2[64 + tid] + rs2[128 + tid] + rs2[192 + tid];
            int   C = rc2[tid] + rc2[64 + tid] + rc2[128 + tid] + rc2[192 + tid];
            rs2[tid] = S * (float)C;
        }
        __syncthreads();
        if (tid == 0) {
            float tot = 0.f;
#pragma unroll
            for (int e2 = 0; e2 < E_EXP; ++e2) tot += rs2[e2];
            out[2 * T_TOK] = tot * (float)E_EXP / ((float)T_TOK * (float)T_TOK);
            g_arrived = 0;   // reset for next graph replay
        }
    }
}

extern "C" void kernel_launch(void* const* d_in, const int* in_sizes, int n_in,
                              void* d_out, int out_size)
{
    const float* inp  = (const float*)d_in[0];
    const float* W    = (const float*)d_in[1];
    const float* bias = (const float*)d_in[2];
    float* out = (float*)d_out;   // [0,T) idx, [T,2T) top1 score, [2T] loss

    cudaFuncSetAttribute(gate_main, cudaFuncAttributeMaxDynamicSharedMemorySize, SMEM_BYTES);
    gate_main<<<NBLK, NT, SMEM_BYTES>>>(inp, W, bias, out);
}

// round 15
// speedup vs baseline: 1.2692x; 1.0645x over previous
#include <cuda_runtime.h>
#include <cuda_fp16.h>
#include <cstdint>

// Problem constants (fixed by the dataset)
#define T_TOK   16384
#define D_DIM   4096
#define E_EXP   64
#define BM      128             // tokens per block
#define BK      64              // fp32 k per chunk (4 k16 steps, kh-split over warp pairs)
#define NCHUNK  (D_DIM / BK)    // 64
#define NBLK    (T_TOK / BM)    // 128
#define NT      256

// fp16 plane tiles, row stride 144 B (128B data + 16B pad -> LDSM conflict-free)
#define RSB       144
#define AH_O      0
#define AL_O      18432          // 128 rows * 144
#define BH_O      36864
#define BL_O      46080          // + 64 * 144
#define STAGE_SZ  55296
#define SMEM_BYTES (2 * STAGE_SZ)   // 110592; Ls[128][65]=33280 overlays stage0

static __device__ float g_ssum[NBLK * E_EXP];
static __device__ int   g_cnt [NBLK * E_EXP];
static __device__ int   g_arrived;   // zero-init; reset by last block each launch

// ---------- helpers ----------
__device__ __forceinline__ uint32_t smem_u32(const void* p) {
    uint32_t a;
    asm("{ .reg .u64 t; cvta.to.shared.u64 t, %1; cvt.u32.u64 %0, t; }" : "=r"(a) : "l"(p));
    return a;
}
__device__ __forceinline__ void cvt_split2(float x0, float x1, uint32_t& h, uint32_t& lo) {
    __half2 hh = __floats2half2_rn(x0, x1);          // low = x0, high = x1
    h = *reinterpret_cast<uint32_t*>(&hh);
    float2 hf = __half22float2(hh);
    __half2 ll = __floats2half2_rn(x0 - hf.x, x1 - hf.y);
    lo = *reinterpret_cast<uint32_t*>(&ll);
}
__device__ __forceinline__ void st2u(uint32_t a, uint32_t x, uint32_t y) {
    asm volatile("st.shared.v2.u32 [%0], {%1,%2};" :: "r"(a), "r"(x), "r"(y));
}
__device__ __forceinline__ void ldsm4(uint32_t a, uint32_t* r) {
    asm volatile("ldmatrix.sync.aligned.m8n8.x4.shared.b16 {%0,%1,%2,%3}, [%4];"
                 : "=r"(r[0]), "=r"(r[1]), "=r"(r[2]), "=r"(r[3]) : "r"(a));
}
__device__ __forceinline__ void mma_f16(float* d, const uint32_t* a, const uint32_t* b) {
    asm volatile(
        "mma.sync.aligned.m16n8k16.row.col.f32.f16.f16.f32 "
        "{%0,%1,%2,%3}, {%4,%5,%6,%7}, {%8,%9}, {%0,%1,%2,%3};"
        : "+f"(d[0]), "+f"(d[1]), "+f"(d[2]), "+f"(d[3])
        : "r"(a[0]), "r"(a[1]), "r"(a[2]), "r"(a[3]), "r"(b[0]), "r"(b[1]));
}

// ---------- single fused kernel ----------
__global__ void __launch_bounds__(NT, 1)
gate_main(const float* __restrict__ inp, const float* __restrict__ W,
          const float* __restrict__ bias, float* __restrict__ out)
{
    extern __shared__ char dsm[];
    __shared__ float s_inv[BM];
    __shared__ float s_ps[NT];
    __shared__ float s_b[E_EXP];
    __shared__ int   s_cnt[E_EXP];
    __shared__ int   s_last;
    __shared__ float rs2[NT];
    __shared__ int   rc2[NT];

    const uint32_t sb = smem_u32(dsm);
    const int tid = threadIdx.x;
    const int blk = blockIdx.x;
    const int w   = tid >> 5;
    const int l   = tid & 31;
    const int l4  = l >> 2;
    const int lk  = l & 3;
    // anti-phase mapping: SMSP = w%4 gets warp w (kh=0) and warp w+4 (kh=1)
    const int kh  = (w >> 2) & 1;   // k16-step pair split AND phase role
    const int tg  = (w >> 1) & 1;   // 2 token groups of 64
    const int eg  = w & 1;          // 2 expert groups of 32

    if (tid < E_EXP) { s_b[tid] = bias[tid]; s_cnt[tid] = 0; }

    // ---- staging: A 2048 f4/chunk / 256 thr = 8 ; W 1024/256 = 4 ----
    const float4* baseA = (const float4*)(inp + (size_t)blk * BM * D_DIM);
    const float4* baseW = (const float4*)W;
    int offA[8]; uint32_t stA[8];
#pragma unroll
    for (int p = 0; p < 8; ++p) {
        int fid = p * NT + tid, row = fid >> 4, q4 = fid & 15;
        offA[p] = row * (D_DIM / 4) + q4;
        stA[p]  = (uint32_t)(row * RSB + q4 * 8);
    }
    int offW[4]; uint32_t stW[4];
#pragma unroll
    for (int p = 0; p < 4; ++p) {
        int fid = p * NT + tid, row = fid >> 4, q4 = fid & 15;
        offW[p] = row * (D_DIM / 4) + q4;
        stW[p]  = (uint32_t)(BH_O + row * RSB + q4 * 8);
    }

    // ---- ldmatrix per-lane base addresses ----
    uint32_t aLd[4];
#pragma unroll
    for (int i = 0; i < 4; ++i)
        aLd[i] = (uint32_t)((tg * 64 + i * 16 + ((l >> 3) & 1) * 8 + (l & 7)) * RSB
                            + (l >> 4) * 16);
    uint32_t bLd[2];
#pragma unroll
    for (int jp = 0; jp < 2; ++jp)
        bLd[jp] = (uint32_t)(BH_O + (eg * 32 + jp * 16 + (l >> 4) * 8 + (l & 7)) * RSB
                             + ((l >> 3) & 1) * 16);

    float acc[4][4][4];
#pragma unroll
    for (int i = 0; i < 4; ++i)
#pragma unroll
        for (int j = 0; j < 4; ++j)
#pragma unroll
            for (int r = 0; r < 4; ++r) acc[i][j][r] = 0.f;

    float4 ra[8], rw[4];

    #define LDG_CHUNK(cc)                                              \
        _Pragma("unroll")                                              \
        for (int p = 0; p < 8; ++p) ra[p] = baseA[offA[p] + (cc) * (BK / 4)]; \
        _Pragma("unroll")                                              \
        for (int p = 0; p < 4; ++p) rw[p] = baseW[offW[p] + (cc) * (BK / 4)];

    #define STS_CHUNK(tb)                                              \
        _Pragma("unroll")                                              \
        for (int p = 0; p < 8; ++p) {                                  \
            uint32_t h01, l01, h23, l23;                               \
            cvt_split2(ra[p].x, ra[p].y, h01, l01);                    \
            cvt_split2(ra[p].z, ra[p].w, h23, l23);                    \
            st2u((tb) + stA[p],        h01, h23);                      \
            st2u((tb) + stA[p] + AL_O, l01, l23);                      \
        }                                                              \
        _Pragma("unroll")                                              \
        for (int p = 0; p < 4; ++p) {                                  \
            uint32_t h01, l01, h23, l23;                               \
            cvt_split2(rw[p].x, rw[p].y, h01, l01);                    \
            cvt_split2(rw[p].z, rw[p].w, h23, l23);                    \
            st2u((tb) + stW[p],                 h01, h23);             \
            st2u((tb) + stW[p] + (BL_O - BH_O), l01, l23);             \
        }

    #define COMPUTE_CHUNK(tb)                                                      \
        _Pragma("unroll")                                                          \
        for (int ks2 = 0; ks2 < 2; ++ks2) {                                        \
            const uint32_t ko = (uint32_t)((kh * 2 + ks2) * 32);                   \
            uint32_t aH[4][4], aL[4][4], bHf[4][2], bLf[4][2];                     \
            _Pragma("unroll")                                                      \
            for (int i = 0; i < 4; ++i) ldsm4((tb) + aLd[i] + ko, aH[i]);          \
            _Pragma("unroll")                                                      \
            for (int jp = 0; jp < 2; ++jp) {                                       \
                uint32_t r[4];                                                     \
                ldsm4((tb) + bLd[jp] + ko, r);                                     \
                bHf[jp * 2][0] = r[0]; bHf[jp * 2][1] = r[1];                      \
                bHf[jp * 2 + 1][0] = r[2]; bHf[jp * 2 + 1][1] = r[3];              \
            }                                                                      \
            _Pragma("unroll")                                                      \
            for (int jp = 0; jp < 2; ++jp) {                                       \
                uint32_t r[4];                                                     \
                ldsm4((tb) + bLd[jp] + ko + (BL_O - BH_O), r);                     \
                bLf[jp * 2][0] = r[0]; bLf[jp * 2][1] = r[1];                      \
                bLf[jp * 2 + 1][0] = r[2]; bLf[jp * 2 + 1][1] = r[3];              \
            }                                                                      \
            _Pragma("unroll")                                                      \
            for (int i = 0; i < 4; ++i) ldsm4((tb) + aLd[i] + ko + AL_O, aL[i]);   \
            _Pragma("unroll")                                                      \
            for (int i = 0; i < 4; ++i)                                            \
                _Pragma("unroll")                                                  \
                for (int j = 0; j < 4; ++j)                                        \
                    mma_f16(acc[i][j], aH[i], bHf[j]);                             \
            _Pragma("unroll")                                                      \
            for (int i = 0; i < 4; ++i)                                            \
                _Pragma("unroll")                                                  \
                for (int j = 0; j < 4; ++j)                                        \
                    mma_f16(acc[i][j], aH[i], bLf[j]);                             \
            _Pragma("unroll")                                                      \
            for (int i = 0; i < 4; ++i)                                            \
                _Pragma("unroll")                                                  \
                for (int j = 0; j < 4; ++j)                                        \
                    mma_f16(acc[i][j], aL[i], bHf[j]);                             \
        }

    // ---- ramp: stage chunk 0, prefetch chunk 1 ----
    LDG_CHUNK(0);
    STS_CHUNK(sb);
    LDG_CHUNK(1);
    __syncthreads();

    for (int c = 0; c < NCHUNK; ++c) {
        const uint32_t tbc = sb + (c & 1) * STAGE_SZ;        // compute buffer
        const uint32_t tbs = sb + ((c + 1) & 1) * STAGE_SZ;  // staging buffer
        // Anti-phase: kh=0 warps stage first then compute; kh=1 warps compute first.
        // Both orders are hazard-free: buf tbs was last read in compute(c-1) (pre-barrier),
        // and both roles finish everything before this chunk's barrier.
        if (kh == 0) {
            if (c + 1 < NCHUNK) {
                STS_CHUNK(tbs);
                if (c + 2 < NCHUNK) { LDG_CHUNK(c + 2); }
            }
            COMPUTE_CHUNK(tbc);
        } else {
            COMPUTE_CHUNK(tbc);
            if (c + 1 < NCHUNK) {
                STS_CHUNK(tbs);
                if (c + 2 < NCHUNK) { LDG_CHUNK(c + 2); }
            }
        }
        __syncthreads();   // everyone done reading buf c&1 and writing buf (c+1)&1
    }

    // ---- epilogue: zero Ls, merge kh pairs via 2-addend atomicAdd (deterministic) ----
    float* Ls = (float*)dsm;   // [128][65], overlays stage0
    for (int idx = tid; idx < BM * 65; idx += NT) Ls[idx] = 0.f;
    __syncthreads();
#pragma unroll
    for (int i = 0; i < 4; ++i) {
        int t0 = tg * 64 + i * 16 + l4;
#pragma unroll
        for (int j = 0; j < 4; ++j) {
            int e0 = eg * 32 + j * 8 + lk * 2;
            atomicAdd(&Ls[t0 * 65 + e0],           acc[i][j][0]);   // 2 commuting addends
            atomicAdd(&Ls[t0 * 65 + e0 + 1],       acc[i][j][1]);
            atomicAdd(&Ls[(t0 + 8) * 65 + e0],     acc[i][j][2]);
            atomicAdd(&Ls[(t0 + 8) * 65 + e0 + 1], acc[i][j][3]);
        }
    }
    __syncthreads();

    // per-token softmax / argmax (threads 0..127); store exp() back
    if (tid < BM) {
        float* lr = &Ls[tid * 65];
        float m = -1e30f; int am = 0;
#pragma unroll
        for (int e = 0; e < E_EXP; ++e) {
            float v = lr[e] + s_b[e];
            lr[e] = v;
            if (v > m) { m = v; am = e; }
        }
        float den = 0.f;
#pragma unroll
        for (int e = 0; e < E_EXP; ++e) {
            float p = expf(lr[e] - m);
            lr[e] = p;
            den += p;
        }
        float inv = 1.f / den;
        s_inv[tid] = inv;
        atomicAdd(&s_cnt[am], 1);          // int atomic: value-deterministic
        int gt = blk * BM + tid;
        out[gt]         = (float)am;       // pruned_idx (capacity 39322 > T: never pruned)
        out[T_TOK + gt] = inv;             // top1 score = exp(0)/den
    }
    __syncthreads();

    // per-expert score partial sums (fixed deterministic order; 4 slices of 32 tokens)
    {
        int e = tid & 63, h = tid >> 6;
        float s = 0.f;
#pragma unroll
        for (int i = 0; i < 32; ++i) {
            int t = h * 32 + i;
            s += Ls[t * 65 + e] * s_inv[t];
        }
        s_ps[tid] = s;
    }
    __syncthreads();
    if (tid < E_EXP) {
        g_ssum[blk * E_EXP + tid] = s_ps[tid] + s_ps[64 + tid] + s_ps[128 + tid] + s_ps[192 + tid];
        g_cnt [blk * E_EXP + tid] = s_cnt[tid];
    }
    __syncthreads();

    // ---- fused loss: last block reduces (deterministic fixed-order) ----
    if (tid == 0) {
        __threadfence();
        int n = atomicAdd(&g_arrived, 1);
        s_last = (n == NBLK - 1) ? 1 : 0;
    }
    __syncthreads();
    if (s_last) {
        __threadfence();
        int e = tid & 63, h = tid >> 6;      // 4 groups of 32 blocks
        float ss = 0.f; int c = 0;
#pragma unroll
        for (int b = h * 32; b < h * 32 + 32; ++b) {
            ss += g_ssum[b * E_EXP + e];
            c  += g_cnt [b * E_EXP + e];
        }
        rs2[tid] = ss; rc2[tid] = c;
        __syncthreads();
        if (tid < E_EXP) {
            float S = rs2[tid] + rs2[64 + tid] + rs2[128 + tid] + rs2[192 + tid];
            int   C = rc2[tid] + rc2[64 + tid] + rc2[128 + tid] + rc2[192 + tid];
            rs2[tid] = S * (float)C;
        }
        __syncthreads();
        if (tid == 0) {
            float tot = 0.f;
#pragma unroll
            for (int e2 = 0; e2 < E_EXP; ++e2) tot += rs2[e2];
            out[2 * T_TOK] = tot * (float)E_EXP / ((float)T_TOK * (float)T_TOK);
            g_arrived = 0;   // reset for next graph replay
        }
    }
}

extern "C" void kernel_launch(void* const* d_in, const int* in_sizes, int n_in,
                              void* d_out, int out_size)
{
    const float* inp  = (const float*)d_in[0];
    const float* W    = (const float*)d_in[1];
    const float* bias = (const float*)d_in[2];
    float* out = (float*)d_out;   // [0,T) idx, [T,2T) top1 score, [2T] loss

    cudaFuncSetAttribute(gate_main, cudaFuncAttributeMaxDynamicSharedMemorySize, SMEM_BYTES);
    gate_main<<<NBLK, NT, SMEM_BYTES>>>(inp, W, bias, out);
}

// round 16
// speedup vs baseline: 1.2724x; 1.0025x over previous
#include <cuda_runtime.h>
#include <cuda_fp16.h>
#include <cstdint>

// Problem constants (fixed by the dataset)
#define T_TOK   16384
#define D_DIM   4096
#define E_EXP   64
#define BM      128             // tokens per block
#define BK      64              // fp32 k per chunk (4 k16 steps, kh-split over warp halves)
#define NCHUNK  (D_DIM / BK)    // 64
#define NBLK    (T_TOK / BM)    // 128
#define NT      512             // 16 warps: 4/SMSP, 2 per phase role

// fp16 plane tiles, row stride 144 B (128B data + 16B pad -> LDSM conflict-free)
#define RSB       144
#define AH_O      0
#define AL_O      18432          // 128 rows * 144
#define BH_O      36864
#define BL_O      46080          // + 64 * 144
#define STAGE_SZ  55296
#define SMEM_BYTES (2 * STAGE_SZ)   // 110592; Ls[128][65]=33280 overlays stage0

static __device__ float g_ssum[NBLK * E_EXP];
static __device__ int   g_cnt [NBLK * E_EXP];
static __device__ int   g_arrived;   // zero-init; reset by last block each launch

// ---------- helpers ----------
__device__ __forceinline__ uint32_t smem_u32(const void* p) {
    uint32_t a;
    asm("{ .reg .u64 t; cvta.to.shared.u64 t, %1; cvt.u32.u64 %0, t; }" : "=r"(a) : "l"(p));
    return a;
}
__device__ __forceinline__ void cvt_split2(float x0, float x1, uint32_t& h, uint32_t& lo) {
    __half2 hh = __floats2half2_rn(x0, x1);          // low = x0, high = x1
    h = *reinterpret_cast<uint32_t*>(&hh);
    float2 hf = __half22float2(hh);
    __half2 ll = __floats2half2_rn(x0 - hf.x, x1 - hf.y);
    lo = *reinterpret_cast<uint32_t*>(&ll);
}
__device__ __forceinline__ void st2u(uint32_t a, uint32_t x, uint32_t y) {
    asm volatile("st.shared.v2.u32 [%0], {%1,%2};" :: "r"(a), "r"(x), "r"(y));
}
__device__ __forceinline__ void ldsm4(uint32_t a, uint32_t* r) {
    asm volatile("ldmatrix.sync.aligned.m8n8.x4.shared.b16 {%0,%1,%2,%3}, [%4];"
                 : "=r"(r[0]), "=r"(r[1]), "=r"(r[2]), "=r"(r[3]) : "r"(a));
}
__device__ __forceinline__ void mma_f16(float* d, const uint32_t* a, const uint32_t* b) {
    asm volatile(
        "mma.sync.aligned.m16n8k16.row.col.f32.f16.f16.f32 "
        "{%0,%1,%2,%3}, {%4,%5,%6,%7}, {%8,%9}, {%0,%1,%2,%3};"
        : "+f"(d[0]), "+f"(d[1]), "+f"(d[2]), "+f"(d[3])
        : "r"(a[0]), "r"(a[1]), "r"(a[2]), "r"(a[3]), "r"(b[0]), "r"(b[1]));
}

// ---------- single fused kernel ----------
__global__ void __launch_bounds__(NT, 1)
gate_main(const float* __restrict__ inp, const float* __restrict__ W,
          const float* __restrict__ bias, float* __restrict__ out)
{
    extern __shared__ char dsm[];
    __shared__ float s_inv[BM];
    __shared__ float s_ps[NT];
    __shared__ float s_b[E_EXP];
    __shared__ int   s_cnt[E_EXP];
    __shared__ int   s_last;
    __shared__ float rs2[NT];
    __shared__ int   rc2[NT];

    const uint32_t sb = smem_u32(dsm);
    const int tid = threadIdx.x;
    const int blk = blockIdx.x;
    const int w   = tid >> 5;
    const int l   = tid & 31;
    const int l4  = l >> 2;
    const int lk  = l & 3;
    // anti-phase: SMSP = w&3 hosts warps {w, w+4, w+8, w+12} -> kh = {0,0,1,1}
    const int kh  = (w >> 3) & 1;   // k16-step pair split AND phase role
    const int tg  = (w >> 1) & 3;   // 4 token groups of 32
    const int eg  = w & 1;          // 2 expert groups of 32

    if (tid < E_EXP) { s_b[tid] = bias[tid]; s_cnt[tid] = 0; }

    // ---- staging: A 2048 f4/chunk / 512 thr = 4 ; W 1024/512 = 2 ----
    const float4* baseA = (const float4*)(inp + (size_t)blk * BM * D_DIM);
    const float4* baseW = (const float4*)W;
    int offA[4]; uint32_t stA[4];
#pragma unroll
    for (int p = 0; p < 4; ++p) {
        int fid = p * NT + tid, row = fid >> 4, q4 = fid & 15;
        offA[p] = row * (D_DIM / 4) + q4;
        stA[p]  = (uint32_t)(row * RSB + q4 * 8);
    }
    int offW[2]; uint32_t stW[2];
#pragma unroll
    for (int p = 0; p < 2; ++p) {
        int fid = p * NT + tid, row = fid >> 4, q4 = fid & 15;
        offW[p] = row * (D_DIM / 4) + q4;
        stW[p]  = (uint32_t)(BH_O + row * RSB + q4 * 8);
    }

    // ---- ldmatrix per-lane base addresses ----
    uint32_t aLd[2];
#pragma unroll
    for (int i = 0; i < 2; ++i)
        aLd[i] = (uint32_t)((tg * 32 + i * 16 + ((l >> 3) & 1) * 8 + (l & 7)) * RSB
                            + (l >> 4) * 16);
    uint32_t bLd[2];
#pragma unroll
    for (int jp = 0; jp < 2; ++jp)
        bLd[jp] = (uint32_t)(BH_O + (eg * 32 + jp * 16 + (l >> 4) * 8 + (l & 7)) * RSB
                             + ((l >> 3) & 1) * 16);

    float acc[2][4][4];
#pragma unroll
    for (int i = 0; i < 2; ++i)
#pragma unroll
        for (int j = 0; j < 4; ++j)
#pragma unroll
            for (int r = 0; r < 4; ++r) acc[i][j][r] = 0.f;

    float4 ra[4], rw[2];

    #define LDG_CHUNK(cc)                                              \
        _Pragma("unroll")                                              \
        for (int p = 0; p < 4; ++p) ra[p] = baseA[offA[p] + (cc) * (BK / 4)]; \
        _Pragma("unroll")                                              \
        for (int p = 0; p < 2; ++p) rw[p] = baseW[offW[p] + (cc) * (BK / 4)];

    #define STS_CHUNK(tb)                                              \
        _Pragma("unroll")                                              \
        for (int p = 0; p < 4; ++p) {                                  \
            uint32_t h01, l01, h23, l23;                               \
            cvt_split2(ra[p].x, ra[p].y, h01, l01);                    \
            cvt_split2(ra[p].z, ra[p].w, h23, l23);                    \
            st2u((tb) + stA[p],        h01, h23);                      \
            st2u((tb) + stA[p] + AL_O, l01, l23);                      \
        }                                                              \
        _Pragma("unroll")                                              \
        for (int p = 0; p < 2; ++p) {                                  \
            uint32_t h01, l01, h23, l23;                               \
            cvt_split2(rw[p].x, rw[p].y, h01, l01);                    \
            cvt_split2(rw[p].z, rw[p].w, h23, l23);                    \
            st2u((tb) + stW[p],                 h01, h23);             \
            st2u((tb) + stW[p] + (BL_O - BH_O), l01, l23);             \
        }

    #define COMPUTE_CHUNK(tb)                                                      \
        _Pragma("unroll")                                                          \
        for (int ks2 = 0; ks2 < 2; ++ks2) {                                        \
            const uint32_t ko = (uint32_t)((kh * 2 + ks2) * 32);                   \
            uint32_t aH[2][4], aL[2][4], bHf[4][2], bLf[4][2];                     \
            _Pragma("unroll")                                                      \
            for (int i = 0; i < 2; ++i) ldsm4((tb) + aLd[i] + ko, aH[i]);          \
            _Pragma("unroll")                                                      \
            for (int jp = 0; jp < 2; ++jp) {                                       \
                uint32_t r[4];                                                     \
                ldsm4((tb) + bLd[jp] + ko, r);                                     \
                bHf[jp * 2][0] = r[0]; bHf[jp * 2][1] = r[1];                      \
                bHf[jp * 2 + 1][0] = r[2]; bHf[jp * 2 + 1][1] = r[3];              \
            }                                                                      \
            _Pragma("unroll")                                                      \
            for (int jp = 0; jp < 2; ++jp) {                                       \
                uint32_t r[4];                                                     \
                ldsm4((tb) + bLd[jp] + ko + (BL_O - BH_O), r);                     \
                bLf[jp * 2][0] = r[0]; bLf[jp * 2][1] = r[1];                      \
                bLf[jp * 2 + 1][0] = r[2]; bLf[jp * 2 + 1][1] = r[3];              \
            }                                                                      \
            _Pragma("unroll")                                                      \
            for (int i = 0; i < 2; ++i) ldsm4((tb) + aLd[i] + ko + AL_O, aL[i]);   \
            _Pragma("unroll")                                                      \
            for (int i = 0; i < 2; ++i)                                            \
                _Pragma("unroll")                                                  \
                for (int j = 0; j < 4; ++j)                                        \
                    mma_f16(acc[i][j], aH[i], bHf[j]);                             \
            _Pragma("unroll")                                                      \
            for (int i = 0; i < 2; ++i)                                            \
                _Pragma("unroll")                                                  \
                for (int j = 0; j < 4; ++j)                                        \
                    mma_f16(acc[i][j], aH[i], bLf[j]);                             \
            _Pragma("unroll")                                                      \
            for (int i = 0; i < 2; ++i)                                            \
                _Pragma("unroll")                                                  \
                for (int j = 0; j < 4; ++j)                                        \
                    mma_f16(acc[i][j], aL[i], bHf[j]);                             \
        }

    // ---- ramp: stage chunk 0, prefetch chunk 1 ----
    LDG_CHUNK(0);
    STS_CHUNK(sb);
    LDG_CHUNK(1);
    __syncthreads();

    for (int c = 0; c < NCHUNK; ++c) {
        const uint32_t tbc = sb + (c & 1) * STAGE_SZ;        // compute buffer
        const uint32_t tbs = sb + ((c + 1) & 1) * STAGE_SZ;  // staging buffer
        // Anti-phase: kh=0 warps stage first then compute; kh=1 warps compute first.
        // Hazard-free: buf tbs was last read in compute(c-1), fenced by the prior sync;
        // both roles finish both actions before this chunk's barrier.
        if (kh == 0) {
            if (c + 1 < NCHUNK) {
                STS_CHUNK(tbs);
                if (c + 2 < NCHUNK) { LDG_CHUNK(c + 2); }
            }
            COMPUTE_CHUNK(tbc);
        } else {
            COMPUTE_CHUNK(tbc);
            if (c + 1 < NCHUNK) {
                STS_CHUNK(tbs);
                if (c + 2 < NCHUNK) { LDG_CHUNK(c + 2); }
            }
        }
        __syncthreads();
    }

    // ---- epilogue: zero Ls, merge kh pairs via 2-addend atomicAdd (deterministic) ----
    float* Ls = (float*)dsm;   // [128][65], overlays stage0
    for (int idx = tid; idx < BM * 65; idx += NT) Ls[idx] = 0.f;
    __syncthreads();
#pragma unroll
    for (int i = 0; i < 2; ++i) {
        int t0 = tg * 32 + i * 16 + l4;
#pragma unroll
        for (int j = 0; j < 4; ++j) {
            int e0 = eg * 32 + j * 8 + lk * 2;
            atomicAdd(&Ls[t0 * 65 + e0],           acc[i][j][0]);   // 2 commuting addends
            atomicAdd(&Ls[t0 * 65 + e0 + 1],       acc[i][j][1]);
            atomicAdd(&Ls[(t0 + 8) * 65 + e0],     acc[i][j][2]);
            atomicAdd(&Ls[(t0 + 8) * 65 + e0 + 1], acc[i][j][3]);
        }
    }
    __syncthreads();

    // per-token softmax / argmax (threads 0..127); store exp() back
    if (tid < BM) {
        float* lr = &Ls[tid * 65];
        float m = -1e30f; int am = 0;
#pragma unroll
        for (int e = 0; e < E_EXP; ++e) {
            float v = lr[e] + s_b[e];
            lr[e] = v;
            if (v > m) { m = v; am = e; }
        }
        float den = 0.f;
#pragma unroll
        for (int e = 0; e < E_EXP; ++e) {
            float p = expf(lr[e] - m);
            lr[e] = p;
            den += p;
        }
        float inv = 1.f / den;
        s_inv[tid] = inv;
        atomicAdd(&s_cnt[am], 1);          // int atomic: value-deterministic
        int gt = blk * BM + tid;
        out[gt]         = (float)am;       // pruned_idx (capacity 39322 > T: never pruned)
        out[T_TOK + gt] = inv;             // top1 score = exp(0)/den
    }
    __syncthreads();

    // per-expert score partial sums (fixed deterministic order; 8 slices of 16 tokens)
    {
        int e = tid & 63, h = tid >> 6;
        float s = 0.f;
#pragma unroll
        for (int i = 0; i < 16; ++i) {
            int t = h * 16 + i;
            s += Ls[t * 65 + e] * s_inv[t];
        }
        s_ps[tid] = s;
    }
    __syncthreads();
    if (tid < E_EXP) {
        float S = 0.f;
#pragma unroll
        for (int g = 0; g < 8; ++g) S += s_ps[g * 64 + tid];
        g_ssum[blk * E_EXP + tid] = S;
        g_cnt [blk * E_EXP + tid] = s_cnt[tid];
    }
    __syncthreads();

    // ---- fused loss: last block reduces (deterministic fixed-order) ----
    if (tid == 0) {
        __threadfence();
        int n = atomicAdd(&g_arrived, 1);
        s_last = (n == NBLK - 1) ? 1 : 0;
    }
    __syncthreads();
    if (s_last) {
        __threadfence();
        int e = tid & 63, h = tid >> 6;      // 8 groups of 16 blocks
        float ss = 0.f; int c = 0;
#pragma unroll
        for (int b = h * 16; b < h * 16 + 16; ++b) {
            ss += g_ssum[b * E_EXP + e];
            c  += g_cnt [b * E_EXP + e];
        }
        rs2[tid] = ss; rc2[tid] = c;
        __syncthreads();
        if (tid < E_EXP) {
            float S = 0.f; int C = 0;
#pragma unroll
            for (int g = 0; g < 8; ++g) { S += rs2[g * 64 + tid]; C += rc2[g * 64 + tid]; }
            rs2[tid] = S * (float)C;
        }
        __syncthreads();
        if (tid == 0) {
            float tot = 0.f;
#pragma unroll
            for (int e2 = 0; e2 < E_EXP; ++e2) tot += rs2[e2];
            out[2 * T_TOK] = tot * (float)E_EXP / ((float)T_TOK * (float)T_TOK);
            g_arrived = 0;   // reset for next graph replay
        }
    }
}

extern "C" void kernel_launch(void* const* d_in, const int* in_sizes, int n_in,
                              void* d_out, int out_size)
{
    const float* inp  = (const float*)d_in[0];
    const float* W    = (const float*)d_in[1];
    const float* bias = (const float*)d_in[2];
    float* out = (float*)d_out;   // [0,T) idx, [T,2T) top1 score, [2T] loss

    cudaFuncSetAttribute(gate_main, cudaFuncAttributeMaxDynamicSharedMemorySize, SMEM_BYTES);
    gate_main<<<NBLK, NT, SMEM_BYTES>>>(inp, W, bias, out);
}